// round 7
// baseline (speedup 1.0000x reference)
#include <cuda_runtime.h>
#include <cuda_bf16.h>
#include <cstdint>
#include <math.h>

#define BB 64
#define TT 1024
#define JJ 128
#define DD 256
#define TM 128   // t rows per CTA tile

// ---------------- device scratch (no runtime alloc allowed) ----------------
__device__ __align__(16) __nv_bfloat16 g_Uhi[BB * JJ * DD];
__device__ __align__(16) __nv_bfloat16 g_Ulo[BB * JJ * DD];
__device__ float g_su[BB * JJ];
__device__ float g_rowmax[BB * TT];
__device__ float g_q2c[BB * DD];

__device__ __forceinline__ void bsplit(float v, uint16_t& hi, uint16_t& lo) {
    __nv_bfloat16 h = __float2bfloat16(v);
    hi = __bfloat16_as_ushort(h);
    lo = __bfloat16_as_ushort(__float2bfloat16(v - __bfloat162float(h)));
}

// mma.sync m16n8k16 bf16 -> f32
__device__ __forceinline__ void mma16816(float* c, const uint32_t* a, const uint32_t* b) {
    asm volatile(
        "mma.sync.aligned.m16n8k16.row.col.f32.bf16.bf16.f32 "
        "{%0,%1,%2,%3}, {%4,%5,%6,%7}, {%8,%9}, {%0,%1,%2,%3};"
        : "+f"(c[0]), "+f"(c[1]), "+f"(c[2]), "+f"(c[3])
        : "r"(a[0]), "r"(a[1]), "r"(a[2]), "r"(a[3]), "r"(b[0]), "r"(b[1]));
}

__device__ __forceinline__ void ldsm4(uint32_t* r, uint32_t addr) {
    asm volatile("ldmatrix.sync.aligned.m8n8.x4.shared.b16 {%0,%1,%2,%3}, [%4];"
        : "=r"(r[0]), "=r"(r[1]), "=r"(r[2]), "=r"(r[3]) : "r"(addr));
}
__device__ __forceinline__ void ldsm4t(uint32_t* r, uint32_t addr) {
    asm volatile("ldmatrix.sync.aligned.m8n8.x4.trans.shared.b16 {%0,%1,%2,%3}, [%4];"
        : "=r"(r[0]), "=r"(r[1]), "=r"(r[2]), "=r"(r[3]) : "r"(addr));
}
#define CP_ASYNC16(dst, src) \
    asm volatile("cp.async.cg.shared.global [%0], [%1], 16;" :: "r"(dst), "l"(src))
#define CP_COMMIT() asm volatile("cp.async.commit_group;" ::: "memory")
#define CP_WAIT0()  asm volatile("cp.async.wait_group 0;" ::: "memory")

// ---------------- smem layout (bytes) ----------------
// SA: A-operand chunk / probs, [128][136] bf16 pitch (272B rows, conflict-free LDSM)
// SB: full U [128 j][264] bf16 pitch (528B rows); reused as f32 epilogue buffer
#define SA_H 0u
#define SA_L 34816u
#define SB_H 69632u
#define SB_L 137216u
#define OFF_SSU 204800u
#define OFF_SSH 205312u
#define OFF_RM  205824u
#define OFF_RS  206848u
#define OFF_WHU 207872u
#define OFF_WH  208896u
#define SMEM_TOTAL 209920u

// ---------------- U split + su precompute ----------------
__global__ void usplit_kernel(const float* __restrict__ U, const float* __restrict__ w_u) {
    __shared__ float sSu[JJ];
    int b = blockIdx.x;
    int tid = threadIdx.x, lane = tid & 31;
    float wu = w_u[tid];
    if (tid < JJ) sSu[tid] = 0.f;
    __syncthreads();
    const float* Ub = U + (size_t)b * JJ * DD;
    __nv_bfloat16* uh = g_Uhi + (size_t)b * JJ * DD;
    __nv_bfloat16* ul = g_Ulo + (size_t)b * JJ * DD;
    for (int j = 0; j < JJ; j++) {
        float v = Ub[j * DD + tid];
        uint16_t hi, lo; bsplit(v, hi, lo);
        uh[j * DD + tid] = __ushort_as_bfloat16(hi);
        ul[j * DD + tid] = __ushort_as_bfloat16(lo);
        float p = v * wu;
        #pragma unroll
        for (int o = 16; o; o >>= 1) p += __shfl_xor_sync(0xffffffffu, p, o);
        if (lane == 0) atomicAdd(&sSu[j], p);
    }
    __syncthreads();
    if (tid < JJ) g_su[b * JJ + tid] = sSu[tid];
}

// ---------------- main fused kernel ----------------
__global__ void __launch_bounds__(256, 1)
bidaf_main(const float* __restrict__ H, const float* __restrict__ w_h,
           const float* __restrict__ w_hu, float* __restrict__ G) {
    extern __shared__ char smem[];
    const uint32_t sbase = (uint32_t)__cvta_generic_to_shared(smem);
    const int b = blockIdx.y;
    const int t0 = blockIdx.x * TM;
    const int tid = threadIdx.x;
    const int wid = tid >> 5, lane = tid & 31;
    const int g = lane >> 2, qt = lane & 3;
    const int l16 = lane & 15, lh = lane >> 4;

    float* sWhu = (float*)(smem + OFF_WHU);
    float* sWh  = (float*)(smem + OFF_WH);
    float* ssu  = (float*)(smem + OFF_SSU);
    float* ssh  = (float*)(smem + OFF_SSH);
    float* sRM  = (float*)(smem + OFF_RM);
    float* sRS  = (float*)(smem + OFF_RS);

    // ---- issue U hi/lo cp.async into SB (full [128][256], pitch 528B) ----
    {
        const char* srcH = (const char*)(g_Uhi + (size_t)b * JJ * DD);
        const char* srcL = (const char*)(g_Ulo + (size_t)b * JJ * DD);
        #pragma unroll
        for (int k = 0; k < 16; k++) {
            int idx = tid + 256 * k;          // 4096 granules of 16B per buffer
            int j = idx >> 5, c = idx & 31;
            uint32_t dst = sbase + (uint32_t)(j * 528 + c * 16);
            CP_ASYNC16(dst + SB_H, srcH + j * 512 + c * 16);
            CP_ASYNC16(dst + SB_L, srcL + j * 512 + c * 16);
        }
        CP_COMMIT();
    }

    sWhu[tid] = w_hu[tid];
    sWh[tid]  = w_h[tid];
    if (tid < JJ) ssu[tid] = g_su[b * JJ + tid];

    const int wm1 = wid >> 1, wn1 = wid & 1;   // GEMM1: 4x2 warp grid, 32x64 tiles
    float C1[2][8][4];
    #pragma unroll
    for (int mf = 0; mf < 2; mf++)
        #pragma unroll
        for (int nf = 0; nf < 8; nf++)
            #pragma unroll
            for (int q = 0; q < 4; q++) C1[mf][nf][q] = 0.f;

    float shreg[16];
    #pragma unroll
    for (int k = 0; k < 16; k++) shreg[k] = 0.f;

    __syncthreads();   // sWhu/sWh visible

    // ================= GEMM1: S[128t][128j], K=256 in 2 A-chunks =================
    for (int ch = 0; ch < 2; ch++) {
        const int d0 = ch * 128;
        // --- stage A-chunk = H*w_hu hi/lo ---
        {
            const float4* H4 = (const float4*)(H + ((size_t)(b * TT + t0)) * DD);
            #pragma unroll
            for (int k = 0; k < 16; k++) {
                int row = wid + 8 * k;
                int d = d0 + lane * 4;
                float4 v = H4[row * 64 + (d >> 2)];
                float a0 = v.x * sWhu[d],     a1 = v.y * sWhu[d + 1];
                float a2 = v.z * sWhu[d + 2], a3 = v.w * sWhu[d + 3];
                uint16_t h0,l0,h1,l1,h2,l2,h3,l3;
                bsplit(a0,h0,l0); bsplit(a1,h1,l1); bsplit(a2,h2,l2); bsplit(a3,h3,l3);
                uint32_t off = (uint32_t)row * 272u + (uint32_t)lane * 8u;
                *(uint2*)(smem + SA_H + off) = make_uint2((uint32_t)h0 | ((uint32_t)h1 << 16),
                                                          (uint32_t)h2 | ((uint32_t)h3 << 16));
                *(uint2*)(smem + SA_L + off) = make_uint2((uint32_t)l0 | ((uint32_t)l1 << 16),
                                                          (uint32_t)l2 | ((uint32_t)l3 << 16));
                float sh = v.x * sWh[d] + v.y * sWh[d + 1] + v.z * sWh[d + 2] + v.w * sWh[d + 3];
                #pragma unroll
                for (int o = 16; o; o >>= 1) sh += __shfl_xor_sync(0xffffffffu, sh, o);
                shreg[k] += sh;
            }
        }
        if (ch == 0) CP_WAIT0();   // U resident before first MMA
        __syncthreads();

        #pragma unroll
        for (int ks = 0; ks < 8; ks++) {
            uint32_t aH[2][4], aL[2][4];
            #pragma unroll
            for (int mf = 0; mf < 2; mf++) {
                uint32_t ar = sbase + (uint32_t)((wm1 * 32 + mf * 16 + l16) * 272 + ks * 32 + lh * 16);
                ldsm4(aH[mf], ar + SA_H);
                ldsm4(aL[mf], ar + SA_L);
            }
            #pragma unroll
            for (int p = 0; p < 4; p++) {
                uint32_t br = sbase + (uint32_t)((wn1 * 64 + p * 16 + l16) * 528
                                                 + ch * 256 + ks * 32 + lh * 16);
                uint32_t bh[4], bl[4];
                ldsm4(bh, br + SB_H);
                ldsm4(bl, br + SB_L);
                // non-trans order: {b0@n0, b0@n1, b1@n0, b1@n1}
                uint32_t B0h[2] = {bh[0], bh[2]}, B1h[2] = {bh[1], bh[3]};
                uint32_t B0l[2] = {bl[0], bl[2]}, B1l[2] = {bl[1], bl[3]};
                #pragma unroll
                for (int mf = 0; mf < 2; mf++) {
                    mma16816(C1[mf][2*p],   aH[mf], B0h);
                    mma16816(C1[mf][2*p],   aL[mf], B0h);
                    mma16816(C1[mf][2*p],   aH[mf], B0l);
                    mma16816(C1[mf][2*p+1], aH[mf], B1h);
                    mma16816(C1[mf][2*p+1], aL[mf], B1h);
                    mma16816(C1[mf][2*p+1], aH[mf], B1l);
                }
            }
        }
        __syncthreads();   // before restaging SA (ch=0) / repacking probs (ch=1)
    }
    if (lane == 0) {
        #pragma unroll
        for (int k = 0; k < 16; k++) ssh[wid + 8 * k] = shreg[k];
    }

    // ================= softmax over j =================
    #pragma unroll
    for (int mf = 0; mf < 2; mf++) {
        int r0 = wm1 * 32 + mf * 16 + g;
        float m0 = -1e30f, m1 = -1e30f;
        #pragma unroll
        for (int nf = 0; nf < 8; nf++) {
            float2 su2 = *(const float2*)&ssu[wn1 * 64 + nf * 8 + qt * 2];
            C1[mf][nf][0] += su2.x; C1[mf][nf][1] += su2.y;
            C1[mf][nf][2] += su2.x; C1[mf][nf][3] += su2.y;
            m0 = fmaxf(m0, fmaxf(C1[mf][nf][0], C1[mf][nf][1]));
            m1 = fmaxf(m1, fmaxf(C1[mf][nf][2], C1[mf][nf][3]));
        }
        #pragma unroll
        for (int o = 1; o < 4; o <<= 1) {
            m0 = fmaxf(m0, __shfl_xor_sync(0xffffffffu, m0, o));
            m1 = fmaxf(m1, __shfl_xor_sync(0xffffffffu, m1, o));
        }
        if (qt == 0) { sRM[r0 * 2 + wn1] = m0; sRM[(r0 + 8) * 2 + wn1] = m1; }
    }
    __syncthreads();
    #pragma unroll
    for (int mf = 0; mf < 2; mf++) {
        int r0 = wm1 * 32 + mf * 16 + g;
        float M0 = fmaxf(sRM[r0 * 2], sRM[r0 * 2 + 1]);
        float M1 = fmaxf(sRM[(r0 + 8) * 2], sRM[(r0 + 8) * 2 + 1]);
        float s0 = 0.f, s1 = 0.f;
        #pragma unroll
        for (int nf = 0; nf < 8; nf++) {
            C1[mf][nf][0] = __expf(C1[mf][nf][0] - M0);
            C1[mf][nf][1] = __expf(C1[mf][nf][1] - M0);
            C1[mf][nf][2] = __expf(C1[mf][nf][2] - M1);
            C1[mf][nf][3] = __expf(C1[mf][nf][3] - M1);
            s0 += C1[mf][nf][0] + C1[mf][nf][1];
            s1 += C1[mf][nf][2] + C1[mf][nf][3];
        }
        #pragma unroll
        for (int o = 1; o < 4; o <<= 1) {
            s0 += __shfl_xor_sync(0xffffffffu, s0, o);
            s1 += __shfl_xor_sync(0xffffffffu, s1, o);
        }
        if (qt == 0) {
            sRS[r0 * 2 + wn1] = s0; sRS[(r0 + 8) * 2 + wn1] = s1;
            if (wn1 == 0) {
                g_rowmax[b * TT + t0 + r0]     = M0 + ssh[r0];
                g_rowmax[b * TT + t0 + r0 + 8] = M1 + ssh[r0 + 8];
            }
        }
    }
    __syncthreads();
    // normalize + pack probs bf16 hi/lo into SA ([t][j], pitch 272B)
    #pragma unroll
    for (int mf = 0; mf < 2; mf++) {
        int r0 = wm1 * 32 + mf * 16 + g;
        float inv0 = 1.f / (sRS[r0 * 2] + sRS[r0 * 2 + 1]);
        float inv1 = 1.f / (sRS[(r0 + 8) * 2] + sRS[(r0 + 8) * 2 + 1]);
        #pragma unroll
        for (int nf = 0; nf < 8; nf++) {
            int col = wn1 * 64 + nf * 8 + qt * 2;
            float p00 = C1[mf][nf][0] * inv0, p01 = C1[mf][nf][1] * inv0;
            float p10 = C1[mf][nf][2] * inv1, p11 = C1[mf][nf][3] * inv1;
            uint16_t h0,l0,h1,l1,h2,l2,h3,l3;
            bsplit(p00,h0,l0); bsplit(p01,h1,l1); bsplit(p10,h2,l2); bsplit(p11,h3,l3);
            uint32_t o0 = (uint32_t)r0 * 272u + (uint32_t)col * 2u;
            uint32_t o1 = (uint32_t)(r0 + 8) * 272u + (uint32_t)col * 2u;
            *(uint32_t*)(smem + SA_H + o0) = (uint32_t)h0 | ((uint32_t)h1 << 16);
            *(uint32_t*)(smem + SA_L + o0) = (uint32_t)l0 | ((uint32_t)l1 << 16);
            *(uint32_t*)(smem + SA_H + o1) = (uint32_t)h2 | ((uint32_t)h3 << 16);
            *(uint32_t*)(smem + SA_L + o1) = (uint32_t)l2 | ((uint32_t)l3 << 16);
        }
    }
    __syncthreads();

    // ================= GEMM2: C2Q[128t][256d] = P @ U, K=j=128 =================
    // B operand read from the SAME U buffer via ldmatrix.trans ([k=j][n=d] -> [n][k])
    const int wm2 = wid >> 2, wn2 = wid & 3;   // 2x4 warp grid, 64x64 tiles
    float C2[4][8][4];
    #pragma unroll
    for (int mf = 0; mf < 4; mf++)
        #pragma unroll
        for (int nf = 0; nf < 8; nf++)
            #pragma unroll
            for (int q = 0; q < 4; q++) C2[mf][nf][q] = 0.f;

    #pragma unroll
    for (int ks = 0; ks < 8; ks++) {
        uint32_t aH[4][4], aL[4][4];
        #pragma unroll
        for (int mf = 0; mf < 4; mf++) {
            uint32_t ar = sbase + (uint32_t)((wm2 * 64 + mf * 16 + l16) * 272 + ks * 32 + lh * 16);
            ldsm4(aH[mf], ar + SA_H);
            ldsm4(aL[mf], ar + SA_L);
        }
        #pragma unroll
        for (int p = 0; p < 4; p++) {
            uint32_t br = sbase + (uint32_t)((ks * 16 + l16) * 528
                                             + (wn2 * 64 + p * 16 + lh * 8) * 2);
            uint32_t bh[4], bl[4];
            ldsm4t(bh, br + SB_H);
            ldsm4t(bl, br + SB_L);
            // trans order: {b0@n0, b1@n0, b0@n1, b1@n1}
            uint32_t B0h[2] = {bh[0], bh[1]}, B1h[2] = {bh[2], bh[3]};
            uint32_t B0l[2] = {bl[0], bl[1]}, B1l[2] = {bl[2], bl[3]};
            #pragma unroll
            for (int mf = 0; mf < 4; mf++) {
                mma16816(C2[mf][2*p],   aH[mf], B0h);
                mma16816(C2[mf][2*p],   aL[mf], B0h);
                mma16816(C2[mf][2*p],   aH[mf], B0l);
                mma16816(C2[mf][2*p+1], aH[mf], B1h);
                mma16816(C2[mf][2*p+1], aL[mf], B1h);
                mma16816(C2[mf][2*p+1], aH[mf], B1l);
            }
        }
    }
    __syncthreads();   // U dead -> SB becomes f32 epilogue buffer

    // ================= epilogue =================
    {
        float* sEpi = (float*)(smem + SB_H);   // [128][264] f32 (135168B = SB region)
        #pragma unroll
        for (int mf = 0; mf < 4; mf++) {
            int r0 = wm2 * 64 + mf * 16 + g;
            #pragma unroll
            for (int nf = 0; nf < 8; nf++) {
                int c0 = wn2 * 64 + nf * 8 + qt * 2;
                *(float2*)&sEpi[r0 * 264 + c0]       = make_float2(C2[mf][nf][0], C2[mf][nf][1]);
                *(float2*)&sEpi[(r0 + 8) * 264 + c0] = make_float2(C2[mf][nf][2], C2[mf][nf][3]);
            }
        }
        __syncthreads();
        #pragma unroll 2
        for (int r = 0; r < 16; r++) {
            int row = wid * 16 + r;
            size_t rowg = (size_t)(b * TT + t0 + row);
            const float* Hrow = H + rowg * DD;
            float* Grow = G + rowg * (4 * DD);
            #pragma unroll
            for (int i = 0; i < 4; i++) {
                int d = 2 * lane + 64 * i;
                float2 cq = *(float2*)&sEpi[row * 264 + d];
                float2 h = *(const float2*)&Hrow[d];
                *(float2*)&Grow[d] = h;
                *(float2*)&Grow[DD + d] = cq;
                *(float2*)&Grow[2 * DD + d] = make_float2(h.x * cq.x, h.y * cq.y);
            }
        }
    }
}

// ---------------- Q2C ----------------
__global__ void q2c_kernel(const float* __restrict__ H) {
    __shared__ float sb[TT];
    __shared__ float red[8];
    int b = blockIdx.x;
    int tid = threadIdx.x;
    int w = tid >> 5, lane = tid & 31;

    float v[4];
    float m = -1e30f;
    #pragma unroll
    for (int k = 0; k < 4; k++) { v[k] = g_rowmax[b * TT + tid + 256 * k]; m = fmaxf(m, v[k]); }
    #pragma unroll
    for (int o = 16; o; o >>= 1) m = fmaxf(m, __shfl_xor_sync(0xffffffffu, m, o));
    if (lane == 0) red[w] = m;
    __syncthreads();
    float M = red[0];
    #pragma unroll
    for (int i = 1; i < 8; i++) M = fmaxf(M, red[i]);
    __syncthreads();

    float sum = 0.f;
    #pragma unroll
    for (int k = 0; k < 4; k++) { float e = __expf(v[k] - M); sb[tid + 256 * k] = e; sum += e; }
    #pragma unroll
    for (int o = 16; o; o >>= 1) sum += __shfl_xor_sync(0xffffffffu, sum, o);
    if (lane == 0) red[w] = sum;
    __syncthreads();
    float S = 0.f;
    #pragma unroll
    for (int i = 0; i < 8; i++) S += red[i];
    float inv = 1.f / S;
    __syncthreads();

    const float* Hb = H + (size_t)b * TT * DD + tid;
    float q = 0.f;
    #pragma unroll 8
    for (int t = 0; t < TT; t++) q += sb[t] * Hb[(size_t)t * DD];
    g_q2c[b * DD + tid] = q * inv;
}

// ---------------- last quarter: G[:,3D:4D] = H * Q2C (4 float4 per thread) ----------------
__global__ void g3_kernel(const float* __restrict__ H, float* __restrict__ G) {
    size_t base = (size_t)blockIdx.x * 1024 + threadIdx.x;
    #pragma unroll
    for (int k = 0; k < 4; k++) {
        size_t idx = base + 256 * k;           // float4 units
        int d4 = (int)(idx & 63);
        size_t bt = idx >> 6;
        int b = (int)(bt >> 10);
        float4 h = ((const float4*)H)[idx];
        float4 q = ((const float4*)g_q2c)[b * 64 + d4];
        float4 o = make_float4(h.x * q.x, h.y * q.y, h.z * q.z, h.w * q.w);
        ((float4*)G)[bt * 256 + 192 + d4] = o;
    }
}

extern "C" void kernel_launch(void* const* d_in, const int* in_sizes, int n_in,
                              void* d_out, int out_size) {
    const float* H    = (const float*)d_in[0];
    const float* U    = (const float*)d_in[1];
    const float* w_h  = (const float*)d_in[2];
    const float* w_u  = (const float*)d_in[3];
    const float* w_hu = (const float*)d_in[4];
    float* G = (float*)d_out;

    cudaFuncSetAttribute(bidaf_main, cudaFuncAttributeMaxDynamicSharedMemorySize, SMEM_TOTAL);

    usplit_kernel<<<BB, 256>>>(U, w_u);
    bidaf_main<<<dim3(TT / TM, BB), 256, SMEM_TOTAL>>>(H, w_h, w_hu, G);
    q2c_kernel<<<BB, 256>>>(H);
    g3_kernel<<<(BB * TT * DD / 4) / 1024, 256>>>(H, G);
}